// round 5
// baseline (speedup 1.0000x reference)
#include <cuda_runtime.h>
#include <cuda_bf16.h>

#define BB   8
#define TT   128
#define EE   30522
#define HH   1000
#define SS   64
#define NZ   10000
#define EN   40522   // E + NZ
#define G4H  4000    // 4*H

// ---------------- static scratch ----------------
__device__ float g_preg[BB*TT*G4H];
__device__ float g_enc [BB*TT*HH];
__device__ float g_nemb[SS*BB*HH];
__device__ float g_n2l [SS*BB*TT];
__device__ float g_Mt  [HH*HH];
__device__ float g_bias2[HH];
__device__ float g_emb [BB*HH];
__device__ float g_applied[BB*HH];
__device__ float g_comb[BB*HH];
__device__ float g_Hs  [SS*BB*HH];
__device__ float g_cA[BB*HH], g_cB[BB*HH];
__device__ float g_hA[BB*HH], g_hB[BB*HH];

__device__ __forceinline__ float sigmoidf_(float x) { return 1.f / (1.f + expf(-x)); }

// ---------------- generic tiled SGEMM ----------------
// C[m*N+n] (+)= sum_k A[m*sAm+k] * W[n*sWn+k*sWk]  (+b1[n] when accumulate==0)
#define BM 128
#define BN 128
#define BK 8
__global__ void __launch_bounds__(256) gemm_kernel(
    const float* __restrict__ A, long long sAm,
    const float* __restrict__ W, long long sWn, long long sWk,
    const float* __restrict__ b1,
    float* __restrict__ C, int M, int N, int K, int kChunk, int accumulate)
{
    __shared__ float As[BK][BM];
    __shared__ float Ws[BK][BN];
    int m0 = blockIdx.y * BM, n0 = blockIdx.x * BN;
    int kBeg = blockIdx.z * kChunk;
    int kEnd = min(K, kBeg + kChunk);
    if (kBeg >= kEnd) return;
    int tid = threadIdx.x;
    int tr = tid >> 4, tc = tid & 15;
    float acc[8][8];
#pragma unroll
    for (int i = 0; i < 8; i++)
#pragma unroll
        for (int j = 0; j < 8; j++) acc[i][j] = 0.f;

    int aM = tid >> 1;          // 0..127
    int aK = (tid & 1) * 4;     // 0 or 4
    int wKK = tid >> 5;         // 0..7
    int wNB = tid & 31;
    bool wK1 = (sWk == 1);

    for (int k0 = kBeg; k0 < kEnd; k0 += BK) {
        {
            int m = m0 + aM;
            const float* ap = A + (long long)m * sAm + (k0 + aK);
#pragma unroll
            for (int i = 0; i < 4; i++) {
                int kk = aK + i;
                As[kk][aM] = (m < M && (k0 + kk) < kEnd) ? ap[i] : 0.f;
            }
        }
        if (wK1) {
            int n = n0 + aM;
            const float* wp = W + (long long)n * sWn + (k0 + aK);
#pragma unroll
            for (int i = 0; i < 4; i++) {
                int kk = aK + i;
                Ws[kk][aM] = (n < N && (k0 + kk) < kEnd) ? wp[i] : 0.f;
            }
        } else {
#pragma unroll
            for (int p = 0; p < 4; p++) {
                int n = n0 + wNB + p * 32;
                float v = 0.f;
                if (n < N && (k0 + wKK) < kEnd)
                    v = W[(long long)n * sWn + (long long)(k0 + wKK) * sWk];
                Ws[wKK][wNB + p * 32] = v;
            }
        }
        __syncthreads();
#pragma unroll
        for (int kk = 0; kk < BK; kk++) {
            float4 a0 = *reinterpret_cast<const float4*>(&As[kk][tr * 4]);
            float4 a1 = *reinterpret_cast<const float4*>(&As[kk][64 + tr * 4]);
            float4 w0 = *reinterpret_cast<const float4*>(&Ws[kk][tc * 4]);
            float4 w1 = *reinterpret_cast<const float4*>(&Ws[kk][64 + tc * 4]);
            float aF[8] = {a0.x,a0.y,a0.z,a0.w,a1.x,a1.y,a1.z,a1.w};
            float wF[8] = {w0.x,w0.y,w0.z,w0.w,w1.x,w1.y,w1.z,w1.w};
#pragma unroll
            for (int i = 0; i < 8; i++)
#pragma unroll
                for (int j = 0; j < 8; j++)
                    acc[i][j] += aF[i] * wF[j];
        }
        __syncthreads();
    }
#pragma unroll
    for (int i = 0; i < 8; i++) {
        int mloc = (i < 4) ? (tr * 4 + i) : (64 + tr * 4 + i - 4);
        int m = m0 + mloc;
        if (m >= M) continue;
#pragma unroll
        for (int j = 0; j < 8; j++) {
            int nloc = (j < 4) ? (tc * 4 + j) : (64 + tc * 4 + j - 4);
            int n = n0 + nloc;
            if (n >= N) continue;
            float v = acc[i][j];
            if (accumulate) atomicAdd(&C[(long long)m * N + n], v);
            else {
                if (b1) v += b1[n];
                C[(long long)m * N + n] = v;
            }
        }
    }
}

// ---------------- skinny GEMM (M<=8), atomicAdd into C ----------------
#define SK_NT 32
#define SK_KC 1024
__global__ void __launch_bounds__(256) skinny_gemm_kernel(
    const float* __restrict__ A, long long sAm,
    const float* __restrict__ W, long long sWn,
    float* __restrict__ C, int M, int N, int K)
{
    __shared__ float As[8][SK_KC];
    int n0 = blockIdx.x * SK_NT;
    int k0 = blockIdx.y * SK_KC;
    int kLen = min(SK_KC, K - k0);
    int tid = threadIdx.x;
    for (int m = 0; m < M; m++)
        for (int k = tid; k < SK_KC; k += 256)
            As[m][k] = (k < kLen) ? A[(long long)m * sAm + k0 + k] : 0.f;
    __syncthreads();
    int warp = tid >> 5, lane = tid & 31;
    if (warp < M) {
        for (int nn = 0; nn < SK_NT; nn++) {
            int n = n0 + nn;
            if (n >= N) break;
            const float* wr = W + (long long)n * sWn + k0;
            float s = 0.f;
            for (int i = lane; i < kLen; i += 32) s += As[warp][i] * wr[i];
#pragma unroll
            for (int o = 16; o; o >>= 1) s += __shfl_xor_sync(0xffffffffu, s, o);
            if (lane == 0) atomicAdd(&C[warp * N + n], s);
        }
    }
}

// ---------------- init / copy ----------------
__global__ void init_kernel(float* dst, const float* b1, const float* b2, int n, int period)
{
    int i = blockIdx.x * 256 + threadIdx.x;
    if (i < n) {
        float v = 0.f; int p = i % period;
        if (b1) v += b1[p];
        if (b2) v += b2[p];
        dst[i] = v;
    }
}
__global__ void copy_hfinal_kernel()
{
    int i = blockIdx.x * 256 + threadIdx.x;
    if (i < BB * HH) {
        int b = i / HH, j = i % HH;
        g_hA[i] = g_enc[(b * TT + TT - 1) * HH + j];
    }
}
__global__ void copy_emb0_kernel()
{
    int i = blockIdx.x * 256 + threadIdx.x;
    if (i < BB * HH) g_emb[i] = g_nemb[i];   // s=0 rows are the first B*H
}

// ---------------- encoder recurrent step ----------------
__global__ void __launch_bounds__(256) enc_step_kernel(const float* __restrict__ Whh, int t)
{
    const float* cIn  = (t & 1) ? g_cB : g_cA;
    float*       cOut = (t & 1) ? g_cA : g_cB;
    int warp = threadIdx.x >> 5, lane = threadIdx.x & 31;
    int j = blockIdx.x * 8 + warp;
    int gate = lane >> 3, b = lane & 7;
    float acc = 0.f;
    if (t > 0) {
        const float* hr = g_enc + (long long)(b * TT + t - 1) * HH;
        const float* wr = Whh + (long long)(gate * HH + j) * HH;
        float a0=0,a1=0,a2=0,a3=0;
#pragma unroll 2
        for (int k = 0; k < HH; k += 4) {
            a0 += hr[k]*wr[k]; a1 += hr[k+1]*wr[k+1];
            a2 += hr[k+2]*wr[k+2]; a3 += hr[k+3]*wr[k+3];
        }
        acc = (a0+a1)+(a2+a3);
    }
    float gv = g_preg[(long long)(b * TT + t) * G4H + gate * HH + j] + acc;
    const unsigned F = 0xffffffffu;
    float gi = __shfl_sync(F, gv, b);
    float gf = __shfl_sync(F, gv, 8 + b);
    float gg = __shfl_sync(F, gv, 16 + b);
    float go = __shfl_sync(F, gv, 24 + b);
    if (gate == 0) {
        float c = sigmoidf_(gf) * cIn[b * HH + j] + sigmoidf_(gi) * tanhf(gg);
        cOut[b * HH + j] = c;
        g_enc[(long long)(b * TT + t) * HH + j] = sigmoidf_(go) * tanhf(c);
    }
}

// ---------------- decoder attention (block per b) ----------------
__global__ void __launch_bounds__(256) dec_attn_kernel(const float* __restrict__ attnW, int s)
{
    const float* hIn = (s & 1) ? g_hB : g_hA;
    __shared__ float sx[2 * HH];
    __shared__ float red[256];
    __shared__ float saw[TT];
    __shared__ float sval;
    int b = blockIdx.x, tid = threadIdx.x;
    for (int k = tid; k < HH; k += 256) {
        sx[k] = g_emb[b * HH + k];
        sx[HH + k] = hIn[b * HH + k];
    }
    __syncthreads();
    int t = tid & 127, half = tid >> 7;
    {
        const float* wr = attnW + (long long)t * (3 * HH) + half * HH;
        const float* xr = sx + half * HH;
        float a0=0,a1=0,a2=0,a3=0;
#pragma unroll 2
        for (int k = 0; k < HH; k += 4) {
            a0 += xr[k]*wr[k]; a1 += xr[k+1]*wr[k+1];
            a2 += xr[k+2]*wr[k+2]; a3 += xr[k+3]*wr[k+3];
        }
        red[tid] = (a0+a1)+(a2+a3);
    }
    __syncthreads();
    if (tid < 128) {
        float l = red[tid] + red[tid + 128] + g_n2l[(s * BB + b) * TT + tid];
        saw[tid] = l; red[tid] = l;
    }
    __syncthreads();
    for (int o = 64; o > 0; o >>= 1) {
        if (tid < o) red[tid] = fmaxf(red[tid], red[tid + o]);
        __syncthreads();
    }
    if (tid == 0) sval = red[0];
    __syncthreads();
    float mx = sval;
    if (tid < 128) { float e = expf(saw[tid] - mx); saw[tid] = e; red[tid] = e; }
    __syncthreads();
    for (int o = 64; o > 0; o >>= 1) {
        if (tid < o) red[tid] += red[tid + o];
        __syncthreads();
    }
    if (tid == 0) sval = red[0];
    __syncthreads();
    float inv = 1.f / sval;
    for (int j = tid; j < HH; j += 256) {
        const float* ep = g_enc + (long long)(b * TT) * HH + j;
        float acc = 0.f;
#pragma unroll 4
        for (int tt = 0; tt < TT; tt++) acc += saw[tt] * ep[(long long)tt * HH];
        g_applied[b * HH + j] = acc * inv;
    }
}

// ---------------- combine + relu ----------------
__global__ void __launch_bounds__(256) dec_comb_kernel(
    const float* __restrict__ combW, const float* __restrict__ combB)
{
    int warp = threadIdx.x >> 5, lane = threadIdx.x & 31;
    int j = blockIdx.x * 8 + warp;
    int b = lane & 7, ch = lane >> 3;
    const float* wr = combW + (long long)j * (2 * HH);
    const float* xe = g_emb + b * HH;
    const float* xa = g_applied + b * HH;
    float s0 = 0.f, s1 = 0.f;
#pragma unroll 2
    for (int i = 0; i < 250; i++) {
        int k = ch + 4 * i;
        s0 += xe[k] * wr[k];
        s1 += xa[k] * wr[HH + k];
    }
    float s = s0 + s1;
    s += __shfl_xor_sync(0xffffffffu, s, 8);
    s += __shfl_xor_sync(0xffffffffu, s, 16);
    if (ch == 0) g_comb[b * HH + j] = fmaxf(s + combB[j], 0.f);
}

// ---------------- decoder LSTM step ----------------
__global__ void __launch_bounds__(256) dec_lstm_kernel(
    const float* __restrict__ Wih, const float* __restrict__ Whh,
    const float* __restrict__ bih, const float* __restrict__ bhh, int s)
{
    const float* hIn  = (s & 1) ? g_hB : g_hA;
    const float* cIn  = (s & 1) ? g_cB : g_cA;
    float*       hOut = (s & 1) ? g_hA : g_hB;
    float*       cOut = (s & 1) ? g_cA : g_cB;
    int warp = threadIdx.x >> 5, lane = threadIdx.x & 31;
    int j = blockIdx.x * 8 + warp;
    int gate = lane >> 3, b = lane & 7;
    int row = gate * HH + j;
    const float* w1 = Wih + (long long)row * HH;
    const float* w2 = Whh + (long long)row * HH;
    const float* x1 = g_comb + b * HH;
    const float* x2 = hIn + b * HH;
    float a0=0,a1=0,a2=0,a3=0;
#pragma unroll 2
    for (int k = 0; k < HH; k += 4) {
        a0 += x1[k]*w1[k] + x2[k]*w2[k];
        a1 += x1[k+1]*w1[k+1] + x2[k+1]*w2[k+1];
        a2 += x1[k+2]*w1[k+2] + x2[k+2]*w2[k+2];
        a3 += x1[k+3]*w1[k+3] + x2[k+3]*w2[k+3];
    }
    float gv = (a0+a1)+(a2+a3) + bih[row] + bhh[row];
    const unsigned F = 0xffffffffu;
    float gi = __shfl_sync(F, gv, b);
    float gf = __shfl_sync(F, gv, 8 + b);
    float gg = __shfl_sync(F, gv, 16 + b);
    float go = __shfl_sync(F, gv, 24 + b);
    if (gate == 0) {
        float c = sigmoidf_(gf) * cIn[b * HH + j] + sigmoidf_(gi) * tanhf(gg);
        float h = sigmoidf_(go) * tanhf(c);
        cOut[b * HH + j] = c;
        hOut[b * HH + j] = h;
        g_Hs[(long long)(s * BB + b) * HH + j] = h;
    }
}

// ---------------- next-step emb via fused Mt ----------------
__global__ void __launch_bounds__(256) dec_embnext_kernel(int s, int snext)
{
    const float* hNew = (s & 1) ? g_hA : g_hB;   // hOut of step s
    int warp = threadIdx.x >> 5, lane = threadIdx.x & 31;
    int j = blockIdx.x * 8 + warp;
    int b = lane & 7, ch = lane >> 3;
    const float* mr = g_Mt + (long long)j * HH;
    const float* hr = hNew + b * HH;
    float s0 = 0.f;
#pragma unroll 2
    for (int i = 0; i < 250; i++) {
        int k = ch + 4 * i;
        s0 += hr[k] * mr[k];
    }
    s0 += __shfl_xor_sync(0xffffffffu, s0, 8);
    s0 += __shfl_xor_sync(0xffffffffu, s0, 16);
    if (ch == 0)
        g_emb[b * HH + j] = s0 + g_bias2[j] + g_nemb[(long long)(snext * BB + b) * HH + j];
}

// ---------------- launcher ----------------
extern "C" void kernel_launch(void* const* d_in, const int* in_sizes, int n_in,
                              void* d_out, int out_size)
{
    const float* input    = (const float*)d_in[0];
    const float* noise1   = (const float*)d_in[2];
    const float* noise2   = (const float*)d_in[3];
    const float* init_dec = (const float*)d_in[4];
    const float* eWih = (const float*)d_in[5];
    const float* eWhh = (const float*)d_in[6];
    const float* ebih = (const float*)d_in[7];
    const float* ebhh = (const float*)d_in[8];
    const float* dWih = (const float*)d_in[9];
    const float* dWhh = (const float*)d_in[10];
    const float* dbih = (const float*)d_in[11];
    const float* dbhh = (const float*)d_in[12];
    const float* embW = (const float*)d_in[13];
    const float* embb = (const float*)d_in[14];
    const float* attW = (const float*)d_in[15];
    const float* attb = (const float*)d_in[16];
    const float* combW = (const float*)d_in[17];
    const float* combb = (const float*)d_in[18];
    const float* outW = (const float*)d_in[19];
    const float* outb = (const float*)d_in[20];
    float* out = (float*)d_out;

    float *preg, *Mt, *nemb, *n2l, *bias2, *emb, *Hs, *cA;
    cudaGetSymbolAddress((void**)&preg,  g_preg);
    cudaGetSymbolAddress((void**)&Mt,    g_Mt);
    cudaGetSymbolAddress((void**)&nemb,  g_nemb);
    cudaGetSymbolAddress((void**)&n2l,   g_n2l);
    cudaGetSymbolAddress((void**)&bias2, g_bias2);
    cudaGetSymbolAddress((void**)&emb,   g_emb);
    cudaGetSymbolAddress((void**)&Hs,    g_Hs);
    cudaGetSymbolAddress((void**)&cA,    g_cA);

    // seeds / bias init
    init_kernel<<<(BB*HH + 255) / 256, 256>>>(cA, nullptr, nullptr, BB*HH, 1);
    init_kernel<<<(BB*TT*G4H + 255) / 256, 256>>>(preg, ebih, ebhh, BB*TT*G4H, G4H);
    init_kernel<<<(HH*HH + 255) / 256, 256>>>(Mt, nullptr, nullptr, HH*HH, 1);
    init_kernel<<<(SS*BB*HH + 255) / 256, 256>>>(nemb, embb, nullptr, SS*BB*HH, HH);
    init_kernel<<<(SS*BB*TT + 255) / 256, 256>>>(n2l, attb, nullptr, SS*BB*TT, TT);
    init_kernel<<<(HH + 255) / 256, 256>>>(bias2, nullptr, nullptr, HH, 1);

    // big batched GEMMs (k-split, accumulate)
    gemm_kernel<<<dim3(32, 8, 4), 256>>>(input, EE, eWih, EE, 1, nullptr,
                                         preg, BB*TT, G4H, EE, 7631, 1);
    gemm_kernel<<<dim3(8, 8, 8), 256>>>(embW, EN, outW, 1, HH, nullptr,
                                        Mt, HH, HH, EE, 3816, 1);
    gemm_kernel<<<dim3(8, 4, 8), 256>>>(noise1, NZ, embW + EE, EN, 1, nullptr,
                                        nemb, SS*BB, HH, NZ, 1250, 1);
    gemm_kernel<<<dim3(1, 4, 16), 256>>>(noise2, HH, attW + 2*HH, 3*HH, 1, nullptr,
                                         n2l, SS*BB, TT, HH, 64, 1);
    // bias2 = emb_W_E @ out_b
    skinny_gemm_kernel<<<dim3(32, 30), 256>>>(outb, 0, embW, EN, bias2, 1, HH, EE);

    // encoder recurrence
    for (int t = 0; t < TT; t++)
        enc_step_kernel<<<125, 256>>>(eWhh, t);
    copy_hfinal_kernel<<<(BB*HH + 255) / 256, 256>>>();

    // decoder step-0 emb
    copy_emb0_kernel<<<(BB*HH + 255) / 256, 256>>>();
    skinny_gemm_kernel<<<dim3(32, 30), 256>>>(init_dec, EE, embW, EN, emb, BB, HH, EE);

    for (int s = 0; s < SS; s++) {
        dec_attn_kernel<<<BB, 256>>>(attW, s);
        dec_comb_kernel<<<125, 256>>>(combW, combb);
        dec_lstm_kernel<<<125, 256>>>(dWih, dWhh, dbih, dbhh, s);
        if (s + 1 < SS) dec_embnext_kernel<<<125, 256>>>(s, s + 1);
    }

    // summary = Hs @ out_W.T + out_b
    gemm_kernel<<<dim3(239, 4, 1), 256>>>(Hs, HH, outW, HH, 1, outb,
                                          out, SS*BB, EE, HH, HH, 0);
}